// round 17
// baseline (speedup 1.0000x reference)
#include <cuda_runtime.h>
#include <cuda_fp16.h>
#include <mma.h>
#include <cstdint>

using namespace nvcuda;

// ---------------------------------------------------------------------------
// PAM, wmma fp16 + selective 2-term splits. Batch-group pipelining:
//   s2:      wqk -> qk -> S(g0) -> reduce(g0) -> S(g1) -> reduce(g1)
//   default: half_x, wd -> v -> [ev0] PV(g0) -> [ev1] PV(g1)
// Groups = batches {0,1} and {2,3}, expressed as pointer offsets.
// ---------------------------------------------------------------------------

#define B_    4
#define NTOK  4096
#define CC    512
#define CRD   64
#define BNTOT (B_ * NTOK)
#define ESHIFT 40.0f

__device__ __half g_qkH[(size_t)BNTOT * 128];
__device__ __half g_qkL[(size_t)BNTOT * 128];
__device__ __half g_xh[(size_t)BNTOT * CC];        // fp16-rounded x
__device__ __half g_vT[(size_t)B_ * CC * NTOK];    // [b][c][tok] fp16
__device__ float  g_S[(size_t)B_ * NTOK * NTOK];   // raw exp probs fp32
__device__ float  g_lpart[(size_t)B_ * 32 * NTOK];
__device__ float  g_mpart[(size_t)B_ * 32 * NTOK];
__device__ float  g_pscale[B_ * NTOK];
__device__ float  g_oscale[B_ * NTOK];
__device__ float  g_WqkT[128 * CC];                // raw fp32
__device__ __half g_WdT16[CC * CC];                // fp16 transposed

__device__ __forceinline__ uint32_t smem_u32(const void* p) {
    uint32_t a;
    asm("{ .reg .u64 t; cvta.to.shared.u64 t, %1; cvt.u32.u64 %0, t; }"
        : "=r"(a) : "l"(p));
    return a;
}
__device__ __forceinline__ void cp16(uint32_t saddr, const void* g) {
    asm volatile("cp.async.cg.shared.global [%0], [%1], 16;" ::"r"(saddr),
                 "l"(g));
}
#define CP_COMMIT() asm volatile("cp.async.commit_group;" ::: "memory")
#define CP_WAIT0()  asm volatile("cp.async.wait_group 0;" ::: "memory")

// ---------------- producers --------------------------------------------------
__global__ void half_x(const float4* __restrict__ in, __half2* __restrict__ o,
                       int n4) {
    int i = blockIdx.x * 256 + threadIdx.x;
    if (i < n4) {
        float4 v = in[i];
        o[i * 2 + 0] = __floats2half2_rn(v.x, v.y);
        o[i * 2 + 1] = __floats2half2_rn(v.z, v.w);
    }
}
__global__ void transpose_wd_h(const float* __restrict__ W,
                               __half* __restrict__ WT) {
    int i = blockIdx.x * 256 + threadIdx.x;
    if (i < CC * CC) {
        int n = i / CC, k = i - n * CC;
        WT[i] = __float2half_rn(W[(size_t)k * CC + n]);
    }
}
__global__ void transpose_wqk(const float* __restrict__ Wb,
                              const float* __restrict__ Wc,
                              float* __restrict__ WT) {
    int i = blockIdx.x * 256 + threadIdx.x;
    if (i < 128 * CC) {
        int n = i / CC, k = i - n * CC;
        WT[i] = (n < CRD) ? Wb[(size_t)k * CRD + n]
                          : Wc[(size_t)k * CRD + (n - CRD)];
    }
}
// n = (#batches in group) * NTOK; pointers pre-offset to group base
__global__ void reduce2(const float* __restrict__ sp,
                        const float* __restrict__ mp,
                        float* __restrict__ pscale,
                        float* __restrict__ oscale, int n) {
    int i = blockIdx.x * 256 + threadIdx.x;
    if (i < n) {
        int b = i >> 12, row = i & (NTOK - 1);
        float s = 0.f, m = 0.f;
#pragma unroll
        for (int j = 0; j < 32; j++) {
            s += sp[((size_t)b * 32 + j) * NTOK + row];
            m = fmaxf(m, mp[((size_t)b * 32 + j) * NTOK + row]);
        }
        float ps = ldexpf(1.f, 14 - ilogbf(m));
        pscale[i] = ps;
        oscale[i] = 1.f / (s * ps);
    }
}

// ---------------- qk GEMM: register-staged fp16 split ------------------------
__global__ __launch_bounds__(256) void gemm_qk_h(const float* __restrict__ A,
                                                 const float* __restrict__ B,
                                                 __half* __restrict__ CH,
                                                 __half* __restrict__ CL) {
    extern __shared__ char smraw[];
    __half* sm = (__half*)smraw;
    constexpr int ASZ = 128 * 40, BSZ = 128 * 40;
    constexpr int STG = 2 * (ASZ + BSZ);
    const int t = threadIdx.x, wid = t >> 5;
    const int warp_m = wid >> 2, warp_n = wid & 3;
    const int by = blockIdx.y;
    const float* At = A + (size_t)(by * 128) * CC;

    wmma::fragment<wmma::accumulator, 16, 16, 16, float> acc[4][2];
#pragma unroll
    for (int i = 0; i < 4; i++)
#pragma unroll
        for (int j = 0; j < 2; j++) wmma::fill_fragment(acc[i][j], 0.f);

    float4 ra[4], rb[4];
    auto ldg = [&](int k0) {
#pragma unroll
        for (int i = 0; i < 4; i++) {
            int id = t + i * 256, r = id >> 3, c = id & 7;
            ra[i] = *(const float4*)&At[(size_t)r * CC + k0 + c * 4];
            rb[i] = *(const float4*)&B[(size_t)r * CC + k0 + c * 4];
        }
    };
    auto sts = [&](int s) {
        __half* AsH = sm + s * STG;
        __half* AsL = AsH + ASZ;
        __half* BsH = AsL + ASZ;
        __half* BsL = BsH + BSZ;
        auto split4 = [](float4 v, __half* dh, __half* dl) {
            __half h;
            h = __float2half_rn(v.x); dh[0] = h;
            dl[0] = __float2half_rn(v.x - __half2float(h));
            h = __float2half_rn(v.y); dh[1] = h;
            dl[1] = __float2half_rn(v.y - __half2float(h));
            h = __float2half_rn(v.z); dh[2] = h;
            dl[2] = __float2half_rn(v.z - __half2float(h));
            h = __float2half_rn(v.w); dh[3] = h;
            dl[3] = __float2half_rn(v.w - __half2float(h));
        };
#pragma unroll
        for (int i = 0; i < 4; i++) {
            int id = t + i * 256, r = id >> 3, c = id & 7;
            split4(ra[i], &AsH[r * 40 + c * 4], &AsL[r * 40 + c * 4]);
            split4(rb[i], &BsH[r * 40 + c * 4], &BsL[r * 40 + c * 4]);
        }
    };

    ldg(0);
    sts(0);
    __syncthreads();

    const int KB = CC / 32;
    for (int kb = 0; kb < KB; kb++) {
        const int p = kb & 1;
        if (kb + 1 < KB) ldg((kb + 1) * 32);
        __half* AsH = sm + p * STG;
        __half* AsL = AsH + ASZ;
        __half* BsH = AsL + ASZ;
        __half* BsL = BsH + BSZ;
#pragma unroll
        for (int ks = 0; ks < 2; ks++) {
            wmma::fragment<wmma::matrix_a, 16, 16, 16, __half,
                           wmma::row_major> faH[4], faL[4];
#pragma unroll
            for (int i = 0; i < 4; i++) {
                int off = (warp_m * 64 + i * 16) * 40 + ks * 16;
                wmma::load_matrix_sync(faH[i], AsH + off, 40);
                wmma::load_matrix_sync(faL[i], AsL + off, 40);
            }
#pragma unroll
            for (int j = 0; j < 2; j++) {
                int off = (warp_n * 32 + j * 16) * 40 + ks * 16;
                wmma::fragment<wmma::matrix_b, 16, 16, 16, __half,
                               wmma::col_major> fbH, fbL;
                wmma::load_matrix_sync(fbH, BsH + off, 40);
                wmma::load_matrix_sync(fbL, BsL + off, 40);
#pragma unroll
                for (int i = 0; i < 4; i++) {
                    wmma::mma_sync(acc[i][j], faH[i], fbL, acc[i][j]);
                    wmma::mma_sync(acc[i][j], faL[i], fbH, acc[i][j]);
                    wmma::mma_sync(acc[i][j], faH[i], fbH, acc[i][j]);
                }
            }
        }
        if (kb + 1 < KB) sts(p ^ 1);
        __syncthreads();
    }

    float* Cs = (float*)smraw;
#pragma unroll
    for (int i = 0; i < 4; i++)
#pragma unroll
        for (int j = 0; j < 2; j++)
            wmma::store_matrix_sync(
                Cs + (warp_m * 64 + i * 16) * 132 + warp_n * 32 + j * 16,
                acc[i][j], 132, wmma::mem_row_major);
    __syncthreads();
    for (int e = t; e < 128 * 32; e += 256) {
        int r = e >> 5, c4 = e & 31;
        float4 v = *(float4*)&Cs[r * 132 + c4 * 4];
        size_t idx = (size_t)(by * 128 + r) * 128 + c4 * 4;
        float vv[4] = {v.x, v.y, v.z, v.w};
#pragma unroll
        for (int q = 0; q < 4; q++) {
            __half h = __float2half_rn(vv[q]);
            CH[idx + q] = h;
            CL[idx + q] = __float2half_rn(vv[q] - __half2float(h));
        }
    }
}

// ---------------- v GEMM (plain fp16, cp.async, K-chunk 64, vT store) -------
__global__ __launch_bounds__(256) void gemm_v16(const __half* __restrict__ A,
                                                const __half* __restrict__ B,
                                                __half* __restrict__ C) {
    extern __shared__ char smraw[];
    __half* sm = (__half*)smraw;
    constexpr int TN = 256;
    constexpr int ASZ = 128 * 72, BSZ = TN * 72;
    constexpr int STG = ASZ + BSZ;
    constexpr int NT = TN / 64;

    const int t = threadIdx.x, wid = t >> 5;
    const int warp_m = wid >> 2, warp_n = wid & 3;
    const int bx = blockIdx.x, by = blockIdx.y;
    const uint32_t smb = smem_u32(smraw);

    const __half* At = A + (size_t)(by * 128) * CC;
    const __half* Bt = B + (size_t)(bx * TN) * CC;

    wmma::fragment<wmma::accumulator, 16, 16, 16, float> acc[4][NT];
#pragma unroll
    for (int i = 0; i < 4; i++)
#pragma unroll
        for (int j = 0; j < NT; j++) wmma::fill_fragment(acc[i][j], 0.f);

    auto issue = [&](int s, int k0) {
        uint32_t ab = smb + s * STG * 2;
        uint32_t bb = ab + ASZ * 2;
#pragma unroll
        for (int i = 0; i < 4; i++) {
            int id = t + i * 256, r = id >> 3, c = id & 7;
            cp16(ab + (r * 72 + c * 8) * 2, At + (size_t)r * CC + k0 + c * 8);
        }
#pragma unroll
        for (int i = 0; i < 8; i++) {
            int id = t + i * 256, r = id >> 3, c = id & 7;
            cp16(bb + (r * 72 + c * 8) * 2, Bt + (size_t)r * CC + k0 + c * 8);
        }
    };

    issue(0, 0);
    CP_COMMIT();
    CP_WAIT0();
    __syncthreads();

    const int KB = CC / 64;
    for (int kb = 0; kb < KB; kb++) {
        const int p = kb & 1;
        if (kb + 1 < KB) {
            issue(p ^ 1, (kb + 1) * 64);
            CP_COMMIT();
        }
        __half* As = sm + p * STG;
        __half* Bs = As + ASZ;
#pragma unroll
        for (int ks = 0; ks < 4; ks++) {
            wmma::fragment<wmma::matrix_a, 16, 16, 16, __half,
                           wmma::row_major> fa[4];
#pragma unroll
            for (int i = 0; i < 4; i++)
                wmma::load_matrix_sync(
                    fa[i], As + (warp_m * 64 + i * 16) * 72 + ks * 16, 72);
#pragma unroll
            for (int j = 0; j < NT; j++) {
                wmma::fragment<wmma::matrix_b, 16, 16, 16, __half,
                               wmma::col_major> fb;
                wmma::load_matrix_sync(
                    fb, Bs + (warp_n * (TN / 4) + j * 16) * 72 + ks * 16, 72);
#pragma unroll
                for (int i = 0; i < 4; i++)
                    wmma::mma_sync(acc[i][j], fa[i], fb, acc[i][j]);
            }
        }
        if (kb + 1 < KB) CP_WAIT0();
        __syncthreads();
    }

    float* Cs = (float*)smraw;
    constexpr int LDCS = TN + 4;
#pragma unroll
    for (int i = 0; i < 4; i++)
#pragma unroll
        for (int j = 0; j < NT; j++)
            wmma::store_matrix_sync(
                Cs + (warp_m * 64 + i * 16) * LDCS + warp_n * (TN / 4) + j * 16,
                acc[i][j], LDCS, wmma::mem_row_major);
    __syncthreads();

    const int tok0 = by * 128;
    const int bglob = tok0 >> 12;
    const int tokin0 = tok0 & (NTOK - 1);
    for (int e = t; e < TN * 32; e += 256) {
        int j = e >> 5, tq = e & 31;
        size_t ob = ((size_t)bglob * CC + bx * TN + j) * NTOK + tokin0 + tq * 4;
        __half2* o2 = (__half2*)&C[ob];
        o2[0] = __floats2half2_rn(Cs[(tq * 4 + 0) * LDCS + j],
                                  Cs[(tq * 4 + 1) * LDCS + j]);
        o2[1] = __floats2half2_rn(Cs[(tq * 4 + 2) * LDCS + j],
                                  Cs[(tq * 4 + 3) * LDCS + j]);
    }
}

// ---------------- S GEMM: single-shot K=64, fp16 split ----------------------
__global__ __launch_bounds__(256) void gemm_s(
    const __half* __restrict__ qkH, const __half* __restrict__ qkL,
    float* __restrict__ C, float* __restrict__ sump,
    float* __restrict__ maxp) {
    extern __shared__ char smraw[];
    __half* sm = (__half*)smraw;
    constexpr int AS = 128 * 72;
    constexpr int BS = 256 * 72;
    const int t = threadIdx.x, wid = t >> 5;
    const int warp_m = wid >> 2, warp_n = wid & 3;
    const int bx = blockIdx.x, by = blockIdx.y, bz = blockIdx.z;
    const uint32_t smb = smem_u32(smraw);

    const __half* AtH = qkH + (size_t)(bz * NTOK + by * 128) * 128;
    const __half* AtL = qkL + (size_t)(bz * NTOK + by * 128) * 128;
    const __half* BtH = qkH + (size_t)(bz * NTOK + bx * 256) * 128 + CRD;
    const __half* BtL = qkL + (size_t)(bz * NTOK + bx * 256) * 128 + CRD;

    const uint32_t aH = smb, aL = smb + AS * 2;
    const uint32_t bH = smb + 2 * AS * 2, bL = smb + (2 * AS + BS) * 2;
#pragma unroll
    for (int i = 0; i < 4; i++) {
        int id = t + i * 256, r = id >> 3, c = id & 7;
        uint32_t so = (r * 72 + c * 8) * 2;
        cp16(aH + so, AtH + (size_t)r * 128 + c * 8);
        cp16(aL + so, AtL + (size_t)r * 128 + c * 8);
    }
#pragma unroll
    for (int i = 0; i < 8; i++) {
        int id = t + i * 256, r = id >> 3, c = id & 7;
        uint32_t so = (r * 72 + c * 8) * 2;
        cp16(bH + so, BtH + (size_t)r * 128 + c * 8);
        cp16(bL + so, BtL + (size_t)r * 128 + c * 8);
    }
    CP_COMMIT();
    CP_WAIT0();
    __syncthreads();

    wmma::fragment<wmma::accumulator, 16, 16, 16, float> acc[4][4];
#pragma unroll
    for (int i = 0; i < 4; i++)
#pragma unroll
        for (int j = 0; j < 4; j++) wmma::fill_fragment(acc[i][j], 0.f);

    __half* AsH = sm;
    __half* AsL = sm + AS;
    __half* BsH = sm + 2 * AS;
    __half* BsL = sm + 2 * AS + BS;
#pragma unroll
    for (int ks = 0; ks < 4; ks++) {
        wmma::fragment<wmma::matrix_a, 16, 16, 16, __half, wmma::row_major>
            faH[4], faL[4];
#pragma unroll
        for (int i = 0; i < 4; i++) {
            int off = (warp_m * 64 + i * 16) * 72 + ks * 16;
            wmma::load_matrix_sync(faH[i], AsH + off, 72);
            wmma::load_matrix_sync(faL[i], AsL + off, 72);
        }
#pragma unroll
        for (int j = 0; j < 4; j++) {
            int off = (warp_n * 64 + j * 16) * 72 + ks * 16;
            wmma::fragment<wmma::matrix_b, 16, 16, 16, __half,
                           wmma::col_major> fbH, fbL;
            wmma::load_matrix_sync(fbH, BsH + off, 72);
            wmma::load_matrix_sync(fbL, BsL + off, 72);
#pragma unroll
            for (int i = 0; i < 4; i++) {
                wmma::mma_sync(acc[i][j], faH[i], fbL, acc[i][j]);
                wmma::mma_sync(acc[i][j], faL[i], fbH, acc[i][j]);
                wmma::mma_sync(acc[i][j], faH[i], fbH, acc[i][j]);
            }
        }
    }
    __syncthreads();  // smem reuse: tiles -> Cs

    float* Cs = (float*)smraw;
    constexpr int LDCS = 260;
#pragma unroll
    for (int i = 0; i < 4; i++)
#pragma unroll
        for (int j = 0; j < 4; j++)
            wmma::store_matrix_sync(
                Cs + (warp_m * 64 + i * 16) * LDCS + warp_n * 64 + j * 16,
                acc[i][j], LDCS, wmma::mem_row_major);
    __syncthreads();

    const int lane = t & 31;
#pragma unroll 4
    for (int it = 0; it < 32; it++) {
        int e = t + it * 256;
        int r = e >> 6, c4 = e & 63;
        float4 v = *(float4*)&Cs[r * LDCS + c4 * 4];
        float4 p;
        p.x = __expf(v.x - ESHIFT);
        p.y = __expf(v.y - ESHIFT);
        p.z = __expf(v.z - ESHIFT);
        p.w = __expf(v.w - ESHIFT);
        float s4 = p.x + p.y + p.z + p.w;
        float m4 = fmaxf(fmaxf(p.x, p.y), fmaxf(p.z, p.w));
        size_t base = (size_t)bz * NTOK * NTOK + (size_t)(by * 128 + r) * NTOK +
                      bx * 256 + c4 * 4;
        *(float4*)&C[base] = p;
#pragma unroll
        for (int o = 16; o; o >>= 1) {
            s4 += __shfl_xor_sync(~0u, s4, o);
            m4 = fmaxf(m4, __shfl_xor_sync(~0u, m4, o));
        }
        if (lane == 0) {
            int slot = bx * 2 + ((c4 >> 5) & 1);
            size_t pi = ((size_t)bz * 32 + slot) * NTOK + by * 128 + r;
            sump[pi] = s4;
            maxp[pi] = m4;
        }
    }
}

// ---------------- PV GEMM: K-chunk 64, interleaved half-staged A ------------
__global__ __launch_bounds__(256) void gemm_pv(
    const float* __restrict__ P, const __half* __restrict__ vT,
    float* __restrict__ C, const float* __restrict__ pscale,
    const float* __restrict__ oscale, const float* __restrict__ xres,
    const float* __restrict__ gamma) {
    extern __shared__ char smraw[];
    __half* sm = (__half*)smraw;
    constexpr int TN = 256;
    constexpr int ASTG = 128 * 72;
    constexpr int BSTG = TN * 72;
    constexpr int STG = ASTG + BSTG;
    constexpr int NT = TN / 64;

    const int t = threadIdx.x, wid = t >> 5;
    const int warp_m = wid >> 2, warp_n = wid & 3;
    const int bx = blockIdx.x, by = blockIdx.y, bz = blockIdx.z;
    const uint32_t smb = smem_u32(smraw);

    const float* At = P + (size_t)bz * NTOK * NTOK + (size_t)(by * 128) * NTOK;
    const __half* Bt = vT + (size_t)bz * CC * NTOK + (size_t)(bx * TN) * NTOK;

    float psc[4];
#pragma unroll
    for (int i = 0; i < 4; i++) {
        int r = (t + i * 256) >> 3;
        psc[i] = pscale[bz * NTOK + by * 128 + r];
    }

    wmma::fragment<wmma::accumulator, 16, 16, 16, float> acc[4][NT];
#pragma unroll
    for (int i = 0; i < 4; i++)
#pragma unroll
        for (int j = 0; j < NT; j++) wmma::fill_fragment(acc[i][j], 0.f);

    float4 ra[4];
    auto ldgA = [&](int k0, int h) {
#pragma unroll
        for (int i = 0; i < 4; i++) {
            int id = t + i * 256, r = id >> 3, c = id & 7;
            ra[i] = *(const float4*)&At[(size_t)r * NTOK + k0 + h * 32 + c * 4];
        }
    };
    auto stsA = [&](int s, int h) {
        __half* As = sm + s * STG;
#pragma unroll
        for (int i = 0; i < 4; i++) {
            int id = t + i * 256, r = id >> 3, c = id & 7;
            __half2* d = (__half2*)&As[r * 72 + h * 32 + c * 4];
            d[0] = __floats2half2_rn(ra[i].x * psc[i], ra[i].y * psc[i]);
            d[1] = __floats2half2_rn(ra[i].z * psc[i], ra[i].w * psc[i]);
        }
    };
    auto issueB = [&](int s, int k0) {
        uint32_t bb = smb + (s * STG + ASTG) * 2;
#pragma unroll
        for (int i = 0; i < 8; i++) {
            int id = t + i * 256, r = id >> 3, c = id & 7;
            cp16(bb + (r * 72 + c * 8) * 2, Bt + (size_t)r * NTOK + k0 + c * 8);
        }
    };

    issueB(0, 0);
    CP_COMMIT();
    ldgA(0, 0);
    stsA(0, 0);
    ldgA(0, 1);
    stsA(0, 1);
    CP_WAIT0();
    __syncthreads();

    const int KB = NTOK / 64;
    for (int kb = 0; kb < KB; kb++) {
        const int p = kb & 1;
        if (kb + 1 < KB) {
            issueB(p ^ 1, (kb + 1) * 64);
            CP_COMMIT();
            ldgA((kb + 1) * 64, 0);
        }
        __half* As = sm + p * STG;
        __half* Bs = As + ASTG;
#pragma unroll
        for (int ks = 0; ks < 4; ks++) {
            wmma::fragment<wmma::matrix_a, 16, 16, 16, __half,
                           wmma::row_major> fa[4];
#pragma unroll
            for (int i = 0; i < 4; i++)
                wmma::load_matrix_sync(
                    fa[i], As + (warp_m * 64 + i * 16) * 72 + ks * 16, 72);
#pragma unroll
            for (int j = 0; j < NT; j++) {
                wmma::fragment<wmma::matrix_b, 16, 16, 16, __half,
                               wmma::col_major> fb;
                wmma::load_matrix_sync(
                    fb, Bs + (warp_n * (TN / 4) + j * 16) * 72 + ks * 16, 72);
#pragma unroll
                for (int i = 0; i < 4; i++)
                    wmma::mma_sync(acc[i][j], fa[i], fb, acc[i][j]);
            }
            if (ks == 1 && kb + 1 < KB) {
                stsA(p ^ 1, 0);
                ldgA((kb + 1) * 64, 1);
            }
        }
        if (kb + 1 < KB) {
            stsA(p ^ 1, 1);
            CP_WAIT0();
        }
        __syncthreads();
    }

    float* Cs = (float*)smraw;
    constexpr int LDCS = TN + 4;
#pragma unroll
    for (int i = 0; i < 4; i++)
#pragma unroll
        for (int j = 0; j < NT; j++)
            wmma::store_matrix_sync(
                Cs + (warp_m * 64 + i * 16) * LDCS + warp_n * (TN / 4) + j * 16,
                acc[i][j], LDCS, wmma::mem_row_major);
    __syncthreads();

    const float g = gamma[0];
    for (int e = t; e < 128 * (TN / 4); e += 256) {
        int r = e / (TN / 4), c4 = e % (TN / 4);
        float4 o = *(float4*)&Cs[r * LDCS + c4 * 4];
        size_t base = (size_t)bz * NTOK * CC + (size_t)(by * 128 + r) * CC +
                      bx * TN + c4 * 4;
        float gl = g * oscale[bz * NTOK + by * 128 + r];
        float4 xr = *(const float4*)&xres[base];
        o.x = gl * o.x + xr.x;
        o.y = gl * o.y + xr.y;
        o.z = gl * o.z + xr.z;
        o.w = gl * o.w + xr.w;
        *(float4*)&C[base] = o;
    }
}

// ---------------------------------------------------------------------------
extern "C" void kernel_launch(void* const* d_in, const int* in_sizes, int n_in,
                              void* d_out, int out_size) {
    const float* x = (const float*)d_in[0];
    const float* Wb = (const float*)d_in[1];
    const float* Wc = (const float*)d_in[2];
    const float* Wd = (const float*)d_in[3];
    const float* gamma = (const float*)d_in[4];
    float* out = (float*)d_out;

    __half *qkH, *qkL, *xh, *vTp, *WdT16;
    float *Sp, *lpart, *mpart, *pscale, *oscale, *WqkT;
    cudaGetSymbolAddress((void**)&qkH, g_qkH);
    cudaGetSymbolAddress((void**)&qkL, g_qkL);
    cudaGetSymbolAddress((void**)&xh, g_xh);
    cudaGetSymbolAddress((void**)&vTp, g_vT);
    cudaGetSymbolAddress((void**)&Sp, g_S);
    cudaGetSymbolAddress((void**)&lpart, g_lpart);
    cudaGetSymbolAddress((void**)&mpart, g_mpart);
    cudaGetSymbolAddress((void**)&pscale, g_pscale);
    cudaGetSymbolAddress((void**)&oscale, g_oscale);
    cudaGetSymbolAddress((void**)&WqkT, g_WqkT);
    cudaGetSymbolAddress((void**)&WdT16, g_WdT16);

    const int smem_qk = 2 * 2 * 2 * (128 + 128) * 40;  // 81920
    const int smem_S = 133120;
    const int smem_v = 133120;
    const int smem_PV = 133120;
    cudaFuncSetAttribute(gemm_qk_h,
                         cudaFuncAttributeMaxDynamicSharedMemorySize, smem_qk);
    cudaFuncSetAttribute(gemm_s,
                         cudaFuncAttributeMaxDynamicSharedMemorySize, smem_S);
    cudaFuncSetAttribute(gemm_v16,
                         cudaFuncAttributeMaxDynamicSharedMemorySize, smem_v);
    cudaFuncSetAttribute(gemm_pv,
                         cudaFuncAttributeMaxDynamicSharedMemorySize, smem_PV);

    // lazily created side stream + fork/join events (host resources only)
    static cudaStream_t s2 = nullptr;
    static cudaEvent_t evb = nullptr, evr[2] = {nullptr, nullptr};
    if (!s2) {
        cudaStreamCreateWithFlags(&s2, cudaStreamNonBlocking);
        cudaEventCreateWithFlags(&evb, cudaEventDisableTiming);
        cudaEventCreateWithFlags(&evr[0], cudaEventDisableTiming);
        cudaEventCreateWithFlags(&evr[1], cudaEventDisableTiming);
    }

    // fork
    cudaEventRecord(evb, 0);
    cudaStreamWaitEvent(s2, evb, 0);

    // s2: qk chain, then per-group S -> reduce
    transpose_wqk<<<(128 * CC + 255) / 256, 256, 0, s2>>>(Wb, Wc, WqkT);
    gemm_qk_h<<<dim3(1, BNTOT / 128), 256, smem_qk, s2>>>(x, WqkT, qkH, qkL);
    for (int g = 0; g < 2; g++) {
        size_t ob = (size_t)g * 2;  // batch offset of group
        gemm_s<<<dim3(NTOK / 256, NTOK / 128, 2), 256, smem_S, s2>>>(
            qkH + ob * NTOK * 128, qkL + ob * NTOK * 128,
            Sp + ob * NTOK * NTOK, lpart + ob * 32 * NTOK,
            mpart + ob * 32 * NTOK);
        reduce2<<<(2 * NTOK + 255) / 256, 256, 0, s2>>>(
            lpart + ob * 32 * NTOK, mpart + ob * 32 * NTOK,
            pscale + ob * NTOK, oscale + ob * NTOK, 2 * NTOK);
        cudaEventRecord(evr[g], s2);
    }

    // default: v chain
    half_x<<<(BNTOT * CC / 4 + 255) / 256, 256>>>((const float4*)x,
                                                  (__half2*)xh,
                                                  BNTOT * CC / 4);
    transpose_wd_h<<<(CC * CC + 255) / 256, 256>>>(Wd, WdT16);
    gemm_v16<<<dim3(CC / 256, BNTOT / 128), 256, smem_v>>>(xh, WdT16, vTp);

    // default: per-group PV after that group's reduce
    for (int g = 0; g < 2; g++) {
        size_t ob = (size_t)g * 2;
        cudaStreamWaitEvent(0, evr[g], 0);
        gemm_pv<<<dim3(CC / 256, NTOK / 128, 2), 256, smem_PV>>>(
            Sp + ob * NTOK * NTOK, vTp + ob * CC * NTOK, out + ob * NTOK * CC,
            pscale + ob * NTOK, oscale + ob * NTOK, x + ob * NTOK * CC, gamma);
    }
}